// round 1
// baseline (speedup 1.0000x reference)
#include <cuda_runtime.h>

// LearnableConvCensus: depthwise 3x3 conv (multiplier 8) -> sigmoid -> mean over 8.
// B=4, C=64, H=W=256, pad=1.
//
// sigmoid(z) = 0.5 + 0.5*tanh(z/2); fold 0.5*temperature[c] into pre-scaled
// weights/bias so the conv accumulator is already tanh's argument.
// out = 0.5 + (sum_m tanh_m) / 16.

#define B_ 4
#define C_ 64
#define H_ 256
#define W_ 256
#define R_ 32                 // output rows per block
#define NROWS (R_ + 2)        // tile rows incl. halo
#define SROW 264              // smem row stride in floats (258 used, padded)

typedef unsigned long long ull;

__device__ __forceinline__ ull pack2(float lo, float hi) {
    ull r;
    asm("mov.b64 %0, {%1, %2};" : "=l"(r) : "f"(lo), "f"(hi));
    return r;
}
__device__ __forceinline__ void unpack2(ull v, float& lo, float& hi) {
    asm("mov.b64 {%0, %1}, %2;" : "=f"(lo), "=f"(hi) : "l"(v));
}
__device__ __forceinline__ ull fma2(ull a, ull b, ull c) {
    ull d;
    asm("fma.rn.f32x2 %0, %1, %2, %3;" : "=l"(d) : "l"(a), "l"(b), "l"(c));
    return d;
}
__device__ __forceinline__ float tanh_fast(float x) {
    float y;
    asm("tanh.approx.f32 %0, %1;" : "=f"(y) : "f"(x));
    return y;
}

__global__ __launch_bounds__(128, 2)
void census_kernel(const float* __restrict__ x, const float* __restrict__ w,
                   const float* __restrict__ bias, const float* __restrict__ temp,
                   float* __restrict__ out) {
    __shared__ float smem[NROWS * SROW];

    const int bid   = blockIdx.x;
    const int strip = bid & 7;          // H_/R_ = 8 strips
    const int c     = (bid >> 3) & 63;
    const int b     = bid >> 9;
    const int h0    = strip * R_;
    const int tid   = threadIdx.x;

    const float* xp = x + ((size_t)(b * C_ + c) * H_) * W_;

    // ---- tile load: smem[r][4 + wcol] = x[h0 + r - 1][wcol]; cols 3 & 260 are
    // the zero conv padding (tiles span the full width). 34*64 float4 / 128 thr.
    #pragma unroll
    for (int i = tid; i < NROWS * 64; i += 128) {
        const int r  = i >> 6;
        const int c4 = (i & 63) << 2;
        const int gh = h0 + r - 1;
        float4 v = make_float4(0.f, 0.f, 0.f, 0.f);
        if (gh >= 0 && gh < H_) v = *(const float4*)(xp + gh * W_ + c4);
        *(float4*)&smem[r * SROW + 4 + c4] = v;
    }
    for (int r = tid; r < NROWS; r += 128) {
        smem[r * SROW + 3]   = 0.f;
        smem[r * SROW + 260] = 0.f;
    }

    // ---- per-channel weights, pre-scaled by 0.5*temperature, as dup f32x2 pairs.
    // w layout HWIO flattened: w[(kh*3+kw)*512 + c*8 + m]
    const float sc = 0.5f * __ldg(&temp[c]);
    ull wd[8][9];
    ull bd[8];
    #pragma unroll
    for (int m = 0; m < 8; m++) {
        #pragma unroll
        for (int k = 0; k < 9; k++) {
            const float wv = __ldg(&w[k * 512 + (c << 3) + m]) * sc;
            wd[m][k] = pack2(wv, wv);
        }
        const float bv = __ldg(&bias[(c << 3) + m]) * sc;
        bd[m] = pack2(bv, bv);
    }
    __syncthreads();

    const int tx = tid & 63;   // 64 threads across width, 4 cols each
    const int ty = tid >> 6;   // 2 row-groups
    float* outp = out + (((size_t)(b * C_ + c) * H_) + h0) * W_ + (tx << 2);

    for (int r = ty; r < R_; r += 2) {
        ull acc[8][2];
        #pragma unroll
        for (int m = 0; m < 8; m++) { acc[m][0] = bd[m]; acc[m][1] = bd[m]; }

        #pragma unroll
        for (int kh = 0; kh < 3; kh++) {
            const float* rowp = &smem[(r + kh) * SROW + (tx << 2)];
            // window W0..W5 = x cols 4tx-1 .. 4tx+4
            const float  wm1 = rowp[3];
            const float4 f4  = *(const float4*)(rowp + 4);
            const float  wp4 = rowp[8];
            const ull pA0 = pack2(wm1,  f4.x);  // pair(0,1) kw=0
            const ull pA1 = pack2(f4.x, f4.y);  // pair(0,1) kw=1
            const ull pA2 = pack2(f4.y, f4.z);  // pair(0,1) kw=2 == pair(2,3) kw=0
            const ull pB1 = pack2(f4.z, f4.w);  // pair(2,3) kw=1
            const ull pB2 = pack2(f4.w, wp4);   // pair(2,3) kw=2
            #pragma unroll
            for (int m = 0; m < 8; m++) {
                acc[m][0] = fma2(pA0, wd[m][kh * 3 + 0], acc[m][0]);
                acc[m][0] = fma2(pA1, wd[m][kh * 3 + 1], acc[m][0]);
                acc[m][0] = fma2(pA2, wd[m][kh * 3 + 2], acc[m][0]);
                acc[m][1] = fma2(pA2, wd[m][kh * 3 + 0], acc[m][1]);
                acc[m][1] = fma2(pB1, wd[m][kh * 3 + 1], acc[m][1]);
                acc[m][1] = fma2(pB2, wd[m][kh * 3 + 2], acc[m][1]);
            }
        }

        float s0 = 0.f, s1 = 0.f, s2 = 0.f, s3 = 0.f;
        #pragma unroll
        for (int m = 0; m < 8; m++) {
            float a0, a1, a2, a3;
            unpack2(acc[m][0], a0, a1);
            unpack2(acc[m][1], a2, a3);
            s0 += tanh_fast(a0);
            s1 += tanh_fast(a1);
            s2 += tanh_fast(a2);
            s3 += tanh_fast(a3);
        }
        float4 o;
        o.x = 0.5f + s0 * 0.0625f;
        o.y = 0.5f + s1 * 0.0625f;
        o.z = 0.5f + s2 * 0.0625f;
        o.w = 0.5f + s3 * 0.0625f;
        *(float4*)(outp + r * W_) = o;
    }
}

extern "C" void kernel_launch(void* const* d_in, const int* in_sizes, int n_in,
                              void* d_out, int out_size) {
    const float* x    = (const float*)d_in[0];
    const float* w    = (const float*)d_in[1];
    const float* bias = (const float*)d_in[2];
    const float* temp = (const float*)d_in[3];
    float* out = (float*)d_out;

    const int grid = B_ * C_ * (H_ / R_);   // 4*64*8 = 2048 blocks
    census_kernel<<<grid, 128>>>(x, w, bias, temp, out);
}

// round 2
// speedup vs baseline: 1.2527x; 1.2527x over previous
#include <cuda_runtime.h>

// LearnableConvCensus: depthwise 3x3 conv (multiplier 8) -> sigmoid -> mean over 8.
// B=4, C=64, H=W=256, pad=1.
//
// sigmoid(z) = 0.5 + 0.5*tanh(z/2); fold 0.5*temperature[c] into pre-scaled
// weights/bias so the conv accumulator is already tanh's argument.
// out = 0.5 + (sum_m tanh_m) / 16.
//
// R2: accumulators pair MULTIPLIERS (m=2p, m=2p+1) with dup'd inputs; fma2 asm
// ties the accumulator in-place ("+l") to kill ALU-pipe MOV traffic.

#define B_ 4
#define C_ 64
#define H_ 256
#define W_ 256
#define R_ 32                 // output rows per block
#define NROWS (R_ + 2)        // tile rows incl. halo
#define SROW 264              // smem row stride in floats (258 used, padded)

typedef unsigned long long ull;

__device__ __forceinline__ ull pack2(float lo, float hi) {
    ull r;
    asm("mov.b64 %0, {%1, %2};" : "=l"(r) : "f"(lo), "f"(hi));
    return r;
}
__device__ __forceinline__ ull dup2(float v) {
    ull r;
    asm("mov.b64 %0, {%1, %1};" : "=l"(r) : "f"(v));
    return r;
}
__device__ __forceinline__ void unpack2(ull v, float& lo, float& hi) {
    asm("mov.b64 {%0, %1}, %2;" : "=f"(lo), "=f"(hi) : "l"(v));
}
__device__ __forceinline__ void fma2(ull& acc, ull a, ull b) {
    asm("fma.rn.f32x2 %0, %1, %2, %0;" : "+l"(acc) : "l"(a), "l"(b));
}
__device__ __forceinline__ float tanh_fast(float x) {
    float y;
    asm("tanh.approx.f32 %0, %1;" : "=f"(y) : "f"(x));
    return y;
}

__global__ __launch_bounds__(128, 3)
void census_kernel(const float* __restrict__ x, const float* __restrict__ w,
                   const float* __restrict__ bias, const float* __restrict__ temp,
                   float* __restrict__ out) {
    __shared__ float smem[NROWS * SROW];

    const int bid   = blockIdx.x;
    const int strip = bid & 7;          // H_/R_ = 8 strips
    const int c     = (bid >> 3) & 63;
    const int b     = bid >> 9;
    const int h0    = strip * R_;
    const int tid   = threadIdx.x;

    const float* xp = x + ((size_t)(b * C_ + c) * H_) * W_;

    // ---- tile load: smem[r][4 + wcol] = x[h0 + r - 1][wcol]; cols 3 & 260 are
    // the zero conv padding (tiles span the full width). 34*64 float4 / 128 thr.
    #pragma unroll
    for (int i = tid; i < NROWS * 64; i += 128) {
        const int r  = i >> 6;
        const int c4 = (i & 63) << 2;
        const int gh = h0 + r - 1;
        float4 v = make_float4(0.f, 0.f, 0.f, 0.f);
        if (gh >= 0 && gh < H_) v = *(const float4*)(xp + gh * W_ + c4);
        *(float4*)&smem[r * SROW + 4 + c4] = v;
    }
    for (int r = tid; r < NROWS; r += 128) {
        smem[r * SROW + 3]   = 0.f;
        smem[r * SROW + 260] = 0.f;
    }

    // ---- per-channel weights, pre-scaled by 0.5*temperature, paired over m:
    // wp[k][p] = (w[m=2p], w[m=2p+1]) for tap k. 36 ull = 72 regs.
    // w layout HWIO flattened: w[(kh*3+kw)*512 + c*8 + m]
    const float sc = 0.5f * __ldg(&temp[c]);
    ull wp[9][4];
    ull bp[4];
    #pragma unroll
    for (int k = 0; k < 9; k++) {
        #pragma unroll
        for (int p = 0; p < 4; p++) {
            const float w0 = __ldg(&w[k * 512 + (c << 3) + 2 * p])     * sc;
            const float w1 = __ldg(&w[k * 512 + (c << 3) + 2 * p + 1]) * sc;
            wp[k][p] = pack2(w0, w1);
        }
    }
    #pragma unroll
    for (int p = 0; p < 4; p++) {
        const float b0 = __ldg(&bias[(c << 3) + 2 * p])     * sc;
        const float b1 = __ldg(&bias[(c << 3) + 2 * p + 1]) * sc;
        bp[p] = pack2(b0, b1);
    }
    __syncthreads();

    const int tx = tid & 63;   // 64 threads across width, 4 cols each
    const int ty = tid >> 6;   // 2 row-groups
    float* outp = out + (((size_t)(b * C_ + c) * H_) + h0) * W_ + (tx << 2);

    for (int r = ty; r < R_; r += 2) {
        // acc[p][j]: multiplier pair p, output column j
        ull acc[4][4];
        #pragma unroll
        for (int p = 0; p < 4; p++) {
            acc[p][0] = bp[p]; acc[p][1] = bp[p];
            acc[p][2] = bp[p]; acc[p][3] = bp[p];
        }

        #pragma unroll
        for (int kh = 0; kh < 3; kh++) {
            const float* rowp = &smem[(r + kh) * SROW + (tx << 2)];
            // window values v[-1..4] = x cols 4tx-1 .. 4tx+4, dup'd as pairs
            const float  wm1 = rowp[3];
            const float4 f4  = *(const float4*)(rowp + 4);
            const float  wp4 = rowp[8];
            ull d[6];
            d[0] = dup2(wm1);
            d[1] = dup2(f4.x);
            d[2] = dup2(f4.y);
            d[3] = dup2(f4.z);
            d[4] = dup2(f4.w);
            d[5] = dup2(wp4);
            #pragma unroll
            for (int kw = 0; kw < 3; kw++) {
                #pragma unroll
                for (int p = 0; p < 4; p++) {
                    const ull wk = wp[kh * 3 + kw][p];
                    fma2(acc[p][0], d[0 + kw], wk);
                    fma2(acc[p][1], d[1 + kw], wk);
                    fma2(acc[p][2], d[2 + kw], wk);
                    fma2(acc[p][3], d[3 + kw], wk);
                }
            }
        }

        float4 o;
        float s[4] = {0.f, 0.f, 0.f, 0.f};
        #pragma unroll
        for (int p = 0; p < 4; p++) {
            #pragma unroll
            for (int j = 0; j < 4; j++) {
                float a0, a1;
                unpack2(acc[p][j], a0, a1);
                s[j] += tanh_fast(a0) + tanh_fast(a1);
            }
        }
        o.x = 0.5f + s[0] * 0.0625f;
        o.y = 0.5f + s[1] * 0.0625f;
        o.z = 0.5f + s[2] * 0.0625f;
        o.w = 0.5f + s[3] * 0.0625f;
        *(float4*)(outp + r * W_) = o;
    }
}

extern "C" void kernel_launch(void* const* d_in, const int* in_sizes, int n_in,
                              void* d_out, int out_size) {
    const float* x    = (const float*)d_in[0];
    const float* w    = (const float*)d_in[1];
    const float* bias = (const float*)d_in[2];
    const float* temp = (const float*)d_in[3];
    float* out = (float*)d_out;

    const int grid = B_ * C_ * (H_ / R_);   // 4*64*8 = 2048 blocks
    census_kernel<<<grid, 128>>>(x, w, bias, temp, out);
}

// round 3
// speedup vs baseline: 1.2557x; 1.0024x over previous
#include <cuda_runtime.h>

// LearnableConvCensus: depthwise 3x3 conv (multiplier 8) -> sigmoid -> mean over 8.
// B=4, C=64, H=W=256, pad=1.
//
// sigmoid(z) = 0.5 + 0.5*tanh(z/2); fold 0.5*temperature[c] into pre-scaled
// weights/bias so the conv accumulator is already tanh's argument.
// out = 0.5 + (sum_m tanh_m) / 16.
//
// R3: weight pairs live in SMEM (broadcast LDS) instead of 72 registers,
// freeing the register file for 4 CTAs/SM (occupancy was the R2 limiter).

#define B_ 4
#define C_ 64
#define H_ 256
#define W_ 256
#define R_ 32                 // output rows per block
#define NROWS (R_ + 2)        // tile rows incl. halo
#define SROW 264              // smem row stride in floats (258 used, padded)

typedef unsigned long long ull;

__device__ __forceinline__ ull pack2(float lo, float hi) {
    ull r;
    asm("mov.b64 %0, {%1, %2};" : "=l"(r) : "f"(lo), "f"(hi));
    return r;
}
__device__ __forceinline__ ull dup2(float v) {
    ull r;
    asm("mov.b64 %0, {%1, %1};" : "=l"(r) : "f"(v));
    return r;
}
__device__ __forceinline__ void unpack2(ull v, float& lo, float& hi) {
    asm("mov.b64 {%0, %1}, %2;" : "=f"(lo), "=f"(hi) : "l"(v));
}
__device__ __forceinline__ void fma2(ull& acc, ull a, ull b) {
    asm("fma.rn.f32x2 %0, %1, %2, %0;" : "+l"(acc) : "l"(a), "l"(b));
}
__device__ __forceinline__ float tanh_fast(float x) {
    float y;
    asm("tanh.approx.f32 %0, %1;" : "=f"(y) : "f"(x));
    return y;
}

__global__ __launch_bounds__(128, 4)
void census_kernel(const float* __restrict__ x, const float* __restrict__ w,
                   const float* __restrict__ bias, const float* __restrict__ temp,
                   float* __restrict__ out) {
    __shared__ float smem[NROWS * SROW];
    __shared__ ull   wsm[9][4];     // weight pairs (m=2p, m=2p+1), pre-scaled
    __shared__ ull   bsm[4];        // bias pairs, pre-scaled

    const int bid   = blockIdx.x;
    const int strip = bid & 7;          // H_/R_ = 8 strips
    const int c     = (bid >> 3) & 63;
    const int b     = bid >> 9;
    const int h0    = strip * R_;
    const int tid   = threadIdx.x;

    const float* xp = x + ((size_t)(b * C_ + c) * H_) * W_;

    // ---- weight prep: w layout HWIO flattened w[(kh*3+kw)*512 + c*8 + m].
    // 36 tap-pairs + 4 bias-pairs, pre-scaled by 0.5*temperature[c].
    if (tid < 40) {
        const float sc = 0.5f * __ldg(&temp[c]);
        if (tid < 36) {
            const int k = tid >> 2, p = tid & 3;
            const float w0 = __ldg(&w[k * 512 + (c << 3) + 2 * p])     * sc;
            const float w1 = __ldg(&w[k * 512 + (c << 3) + 2 * p + 1]) * sc;
            wsm[k][p] = pack2(w0, w1);
        } else {
            const int p = tid - 36;
            const float b0 = __ldg(&bias[(c << 3) + 2 * p])     * sc;
            const float b1 = __ldg(&bias[(c << 3) + 2 * p + 1]) * sc;
            bsm[p] = pack2(b0, b1);
        }
    }

    // ---- tile load: smem[r][4 + wcol] = x[h0 + r - 1][wcol]; cols 3 & 260 are
    // the zero conv padding (tiles span the full width). 34*64 float4 / 128 thr.
    #pragma unroll
    for (int i = tid; i < NROWS * 64; i += 128) {
        const int r  = i >> 6;
        const int c4 = (i & 63) << 2;
        const int gh = h0 + r - 1;
        float4 v = make_float4(0.f, 0.f, 0.f, 0.f);
        if (gh >= 0 && gh < H_) v = *(const float4*)(xp + gh * W_ + c4);
        *(float4*)&smem[r * SROW + 4 + c4] = v;
    }
    for (int r = tid; r < NROWS; r += 128) {
        smem[r * SROW + 3]   = 0.f;
        smem[r * SROW + 260] = 0.f;
    }
    __syncthreads();

    // bias pairs resident in registers (8 regs)
    ull bp0 = bsm[0], bp1 = bsm[1], bp2 = bsm[2], bp3 = bsm[3];

    const int tx = tid & 63;   // 64 threads across width, 4 cols each
    const int ty = tid >> 6;   // 2 row-groups
    float* outp = out + (((size_t)(b * C_ + c) * H_) + h0) * W_ + (tx << 2);

    #pragma unroll 1
    for (int r = ty; r < R_; r += 2) {
        // acc[p][j]: multiplier pair p, output column j
        ull acc[4][4];
        #pragma unroll
        for (int j = 0; j < 4; j++) {
            acc[0][j] = bp0; acc[1][j] = bp1;
            acc[2][j] = bp2; acc[3][j] = bp3;
        }

        #pragma unroll
        for (int kh = 0; kh < 3; kh++) {
            const float* rowp = &smem[(r + kh) * SROW + (tx << 2)];
            // window values v[-1..4] = x cols 4tx-1 .. 4tx+4, dup'd as pairs
            const float  wm1 = rowp[3];
            const float4 f4  = *(const float4*)(rowp + 4);
            const float  wp4 = rowp[8];
            ull d[6];
            d[0] = dup2(wm1);
            d[1] = dup2(f4.x);
            d[2] = dup2(f4.y);
            d[3] = dup2(f4.z);
            d[4] = dup2(f4.w);
            d[5] = dup2(wp4);
            #pragma unroll
            for (int kw = 0; kw < 3; kw++) {
                #pragma unroll
                for (int p = 0; p < 4; p++) {
                    const ull wk = wsm[kh * 3 + kw][p];   // broadcast LDS.64
                    fma2(acc[p][0], d[0 + kw], wk);
                    fma2(acc[p][1], d[1 + kw], wk);
                    fma2(acc[p][2], d[2 + kw], wk);
                    fma2(acc[p][3], d[3 + kw], wk);
                }
            }
        }

        float4 o;
        float s[4] = {0.f, 0.f, 0.f, 0.f};
        #pragma unroll
        for (int p = 0; p < 4; p++) {
            #pragma unroll
            for (int j = 0; j < 4; j++) {
                float a0, a1;
                unpack2(acc[p][j], a0, a1);
                s[j] += tanh_fast(a0) + tanh_fast(a1);
            }
        }
        o.x = 0.5f + s[0] * 0.0625f;
        o.y = 0.5f + s[1] * 0.0625f;
        o.z = 0.5f + s[2] * 0.0625f;
        o.w = 0.5f + s[3] * 0.0625f;
        *(float4*)(outp + r * W_) = o;
    }
}

extern "C" void kernel_launch(void* const* d_in, const int* in_sizes, int n_in,
                              void* d_out, int out_size) {
    const float* x    = (const float*)d_in[0];
    const float* w    = (const float*)d_in[1];
    const float* bias = (const float*)d_in[2];
    const float* temp = (const float*)d_in[3];
    float* out = (float*)d_out;

    const int grid = B_ * C_ * (H_ / R_);   // 4*64*8 = 2048 blocks
    census_kernel<<<grid, 128>>>(x, w, bias, temp, out);
}

// round 4
// speedup vs baseline: 1.4322x; 1.1405x over previous
#include <cuda_runtime.h>

// LearnableConvCensus: depthwise 3x3 conv (multiplier 8) -> sigmoid -> mean over 8.
// B=4, C=64, H=W=256, pad=1.
//
// sigmoid(z) = 0.5 + 0.5*tanh(z/2); fold 0.5*temperature[c] into pre-scaled
// weights/bias. out = 0.5 + (sum_m tanh_m) / 16.
//
// R4: software-pipelined epilogue — tanh/MUFU of row r overlaps the FMA burst
// of row r+2 (breaks the FMA-phase/MUFU-phase lockstep that halved both pipes).
// Weight pairs fetched as LDS.128 (ulonglong2).

#define B_ 4
#define C_ 64
#define H_ 256
#define W_ 256
#define R_ 32                 // output rows per block
#define NROWS (R_ + 2)        // tile rows incl. halo
#define SROW 264              // smem row stride in floats

typedef unsigned long long ull;

__device__ __forceinline__ ull pack2(float lo, float hi) {
    ull r;
    asm("mov.b64 %0, {%1, %2};" : "=l"(r) : "f"(lo), "f"(hi));
    return r;
}
__device__ __forceinline__ ull dup2(float v) {
    ull r;
    asm("mov.b64 %0, {%1, %1};" : "=l"(r) : "f"(v));
    return r;
}
__device__ __forceinline__ void unpack2(ull v, float& lo, float& hi) {
    asm("mov.b64 {%0, %1}, %2;" : "=f"(lo), "=f"(hi) : "l"(v));
}
__device__ __forceinline__ void fma2(ull& acc, ull a, ull b) {
    asm("fma.rn.f32x2 %0, %1, %2, %0;" : "+l"(acc) : "l"(a), "l"(b));
}
__device__ __forceinline__ float tanh_fast(float x) {
    float y;
    asm("tanh.approx.f32 %0, %1;" : "=f"(y) : "f"(x));
    return y;
}

__global__ __launch_bounds__(128, 4)
void census_kernel(const float* __restrict__ x, const float* __restrict__ w,
                   const float* __restrict__ bias, const float* __restrict__ temp,
                   float* __restrict__ out) {
    __shared__ float      smem[NROWS * SROW];
    __shared__ ulonglong2 wsm2[9][2];   // [k][0]=(pair0,pair1), [k][1]=(pair2,pair3)
    __shared__ ull        bsm[4];

    const int bid   = blockIdx.x;
    const int strip = bid & 7;          // H_/R_ = 8 strips
    const int c     = (bid >> 3) & 63;
    const int b     = bid >> 9;
    const int h0    = strip * R_;
    const int tid   = threadIdx.x;

    const float* xp = x + ((size_t)(b * C_ + c) * H_) * W_;

    // ---- weight prep: w layout HWIO flattened w[(kh*3+kw)*512 + c*8 + m]
    if (tid < 40) {
        const float sc = 0.5f * __ldg(&temp[c]);
        if (tid < 36) {
            const int k = tid >> 2, p = tid & 3;
            const float w0 = __ldg(&w[k * 512 + (c << 3) + 2 * p])     * sc;
            const float w1 = __ldg(&w[k * 512 + (c << 3) + 2 * p + 1]) * sc;
            ((ull*)wsm2)[k * 4 + p] = pack2(w0, w1);
        } else {
            const int p = tid - 36;
            const float b0 = __ldg(&bias[(c << 3) + 2 * p])     * sc;
            const float b1 = __ldg(&bias[(c << 3) + 2 * p + 1]) * sc;
            bsm[p] = pack2(b0, b1);
        }
    }

    // ---- tile load: smem[r][4 + wcol] = x[h0 + r - 1][wcol]; cols 3 & 260 are
    // the zero conv padding (tiles span the full width).
    #pragma unroll
    for (int i = tid; i < NROWS * 64; i += 128) {
        const int r  = i >> 6;
        const int c4 = (i & 63) << 2;
        const int gh = h0 + r - 1;
        float4 v = make_float4(0.f, 0.f, 0.f, 0.f);
        if (gh >= 0 && gh < H_) v = *(const float4*)(xp + gh * W_ + c4);
        *(float4*)&smem[r * SROW + 4 + c4] = v;
    }
    for (int r = tid; r < NROWS; r += 128) {
        smem[r * SROW + 3]   = 0.f;
        smem[r * SROW + 260] = 0.f;
    }
    __syncthreads();

    const ull bp0 = bsm[0], bp1 = bsm[1], bp2 = bsm[2], bp3 = bsm[3];

    const int tx = tid & 63;   // 64 threads across width, 4 cols each
    const int ty = tid >> 6;   // 2 row-groups
    float* outp = out + (((size_t)(b * C_ + c) * H_) + h0) * W_ + (tx << 2);

    // conv of one output row into acc[p][j] (p = multiplier pair, j = column)
    auto conv = [&](int r, ull acc[4][4]) {
        #pragma unroll
        for (int j = 0; j < 4; j++) {
            acc[0][j] = bp0; acc[1][j] = bp1;
            acc[2][j] = bp2; acc[3][j] = bp3;
        }
        #pragma unroll
        for (int kh = 0; kh < 3; kh++) {
            const float* rowp = &smem[(r + kh) * SROW + (tx << 2)];
            const float  wm1 = rowp[3];
            const float4 f4  = *(const float4*)(rowp + 4);
            const float  wp4 = rowp[8];
            ull d[6];
            d[0] = dup2(wm1);
            d[1] = dup2(f4.x);
            d[2] = dup2(f4.y);
            d[3] = dup2(f4.z);
            d[4] = dup2(f4.w);
            d[5] = dup2(wp4);
            #pragma unroll
            for (int kw = 0; kw < 3; kw++) {
                const ulonglong2 w01 = wsm2[kh * 3 + kw][0];  // LDS.128
                const ulonglong2 w23 = wsm2[kh * 3 + kw][1];  // LDS.128
                #pragma unroll
                for (int j = 0; j < 4; j++) {
                    fma2(acc[0][j], d[j + kw], w01.x);
                    fma2(acc[1][j], d[j + kw], w01.y);
                    fma2(acc[2][j], d[j + kw], w23.x);
                    fma2(acc[3][j], d[j + kw], w23.y);
                }
            }
        }
    };

    auto epi = [&](ull acc[4][4], int r) {
        float s[4] = {0.f, 0.f, 0.f, 0.f};
        #pragma unroll
        for (int p = 0; p < 4; p++) {
            #pragma unroll
            for (int j = 0; j < 4; j++) {
                float a0, a1;
                unpack2(acc[p][j], a0, a1);
                s[j] += tanh_fast(a0) + tanh_fast(a1);
            }
        }
        float4 o;
        o.x = 0.5f + s[0] * 0.0625f;
        o.y = 0.5f + s[1] * 0.0625f;
        o.z = 0.5f + s[2] * 0.0625f;
        o.w = 0.5f + s[3] * 0.0625f;
        *(float4*)(outp + r * W_) = o;
    };

    // software pipeline: epi(row k) overlaps conv(row k+1)
    ull accA[4][4], accB[4][4];
    int r = ty;
    conv(r, accA);
    #pragma unroll 1
    for (int i = 0; i < 7; i++) {
        conv(r + 2, accB);
        epi(accA, r);
        conv(r + 4, accA);
        epi(accB, r + 2);
        r += 4;
    }
    conv(r + 2, accB);
    epi(accA, r);
    epi(accB, r + 2);
}

extern "C" void kernel_launch(void* const* d_in, const int* in_sizes, int n_in,
                              void* d_out, int out_size) {
    const float* x    = (const float*)d_in[0];
    const float* w    = (const float*)d_in[1];
    const float* bias = (const float*)d_in[2];
    const float* temp = (const float*)d_in[3];
    float* out = (float*)d_out;

    const int grid = B_ * C_ * (H_ / R_);   // 4*64*8 = 2048 blocks
    census_kernel<<<grid, 128>>>(x, w, bias, temp, out);
}